// round 16
// baseline (speedup 1.0000x reference)
#include <cuda_runtime.h>
#include <cuda_fp16.h>
#include <math.h>
#include <cstdint>

#define BATCH 16384
#define NEXP  5

#define KP_MOE1  4160   // 5 * 832
#define KPE1     832
#define KP_MOE23 1600   // 5 * 320
#define KPE23    320
#define KP_GATE1 576
#define PH_STR   528

// ---------------- scratch (static device globals; no allocation) ------------
__device__ __half d_Ih  [(size_t)BATCH * 2048];
__device__ __half d_zh  [BATCH * 32];
__device__ __half d_ph  [(size_t)BATCH * PH_STR + 64];
__device__ __half d_bufA[BATCH * 256];            // inet ping / ienc
__device__ __half d_bufB[BATCH * 256];
__device__ float  d_omega[BATCH * NEXP];
__device__ __half d_h1  [BATCH * 256 + 64];
__device__ __half d_h2  [BATCH * 256 + 64];
// transposed half weights [N][KP]
__device__ __half d_tiw1[256 * 2048], d_tiw2[256 * 256], d_tiw3[256 * 256];
__device__ __half d_tgw1[256 * KP_GATE1], d_tgw2[128 * 256];
__device__ __half d_twl1[256 * KP_MOE1], d_twl2[256 * KP_MOE23], d_twl3[524 * KP_MOE23];

// ---------------- helpers ----------------------------------------------------
__device__ __forceinline__ void mma16(float* d, const uint32_t* a, const uint32_t* b) {
    asm volatile(
        "mma.sync.aligned.m16n8k16.row.col.f32.f16.f16.f32 "
        "{%0,%1,%2,%3}, {%4,%5,%6,%7}, {%8,%9}, {%0,%1,%2,%3};"
        : "+f"(d[0]), "+f"(d[1]), "+f"(d[2]), "+f"(d[3])
        : "r"(a[0]), "r"(a[1]), "r"(a[2]), "r"(a[3]), "r"(b[0]), "r"(b[1]));
}
__device__ __forceinline__ void ldsm4(uint32_t* r, uint32_t addr) {
    asm volatile("ldmatrix.sync.aligned.m8n8.x4.shared.b16 {%0,%1,%2,%3}, [%4];"
                 : "=r"(r[0]), "=r"(r[1]), "=r"(r[2]), "=r"(r[3]) : "r"(addr));
}
__device__ __forceinline__ void cp16(uint32_t dst, const void* src, bool ok) {
    asm volatile("cp.async.cg.shared.global [%0], [%1], 16, %2;"
                 :: "r"(dst), "l"(src), "r"(ok ? 16 : 0) : "memory");
}
__device__ __forceinline__ void cp_commit() {
    asm volatile("cp.async.commit_group;" ::: "memory");
}
template <int NPEND> __device__ __forceinline__ void cp_wait() {
    asm volatile("cp.async.wait_group %0;" :: "n"(NPEND) : "memory");
}
__device__ __forceinline__ uint32_t hmul2u(uint32_t a, uint32_t s) {
    __half2 ha = *(__half2*)&a;
    __half2 hs = *(__half2*)&s;
    __half2 r = __hmul2(ha, hs);
    return *(uint32_t*)&r;
}

// ---------------- fp16 tensor-core GEMM (R10 champion core) ------------------
// Block 128x128x64, 256 threads, warps 2x4, warp tile 64x32.
// Single-__syncthreads double-buffered cp.async mainloop.
// CONCAT 0: A'[m,k]=A[m*lda+k]
// CONCAT 1: gate1 concat  (zh:32 | ph strided)
// CONCAT 3: moe1 expert blocks of 832: z(32)|ienc(256)|p(524)|bias1|pad
// CONCAT 4: moe23 expert blocks of 320: z(32)|h(256)|bias1|pad
// SCALED: scale A fragments by omega[row][e], e = chunk/CPE; expert's last
//         chunk carries a 1.0 column at BCOL (bias row of Wt).
// SMAX: replace epilogue with 128->5 projection (gw3,gb3) + softmax -> omega_out
template <int CONCAT, bool SCALED, int CPE, int BCOL, bool HAS_BIAS, bool DO_ELU,
          bool OUT_HALF, bool SMAX>
__global__ __launch_bounds__(256, 2)
void mma_gemm(const __half* __restrict__ A, int lda,
              const __half* __restrict__ S1, const __half* __restrict__ S2,
              const __half* __restrict__ S3,
              const float* __restrict__ omega,
              const __half* __restrict__ Wt, const float* __restrict__ bias,
              const float* __restrict__ gw3, const float* __restrict__ gb3,
              float* __restrict__ omega_out,
              void* __restrict__ C, int ldc, int N, int K)
{
    constexpr int ASTAGE = 128 * 72;   // halves
    constexpr int BSTAGE = 128 * 72;
    extern __shared__ __half smh[];
    __half* As = smh;
    __half* Bs = smh + 2 * ASTAGE;
    float*  ws = (float*)(smh + 4 * ASTAGE);   // 128 x 5 omega

    const int tid    = threadIdx.x;
    const int wid    = tid >> 5;
    const int lane   = tid & 31;
    const int warp_m = wid & 1;
    const int warp_n = wid >> 1;
    const int bm     = blockIdx.y * 128;
    const int n0     = blockIdx.x * 128;
    const int r0     = lane >> 2;
    const int c0     = lane & 3;

    const uint32_t sA = (uint32_t)__cvta_generic_to_shared(As);
    const uint32_t sB = (uint32_t)__cvta_generic_to_shared(Bs);

    const int lrow  = warp_m * 64 + (lane & 7) + ((lane >> 3) & 1) * 8;
    const int alcol = (lane >> 4) * 8;

    float d[4][4][4];
#pragma unroll
    for (int mt = 0; mt < 4; mt++)
#pragma unroll
        for (int nt = 0; nt < 4; nt++)
#pragma unroll
            for (int r = 0; r < 4; r++) d[mt][nt][r] = 0.f;

    const int NC = K >> 6;

    auto issue = [&](int c) {
        const int kb  = c * 64;
        const int buf = c & 1;
#pragma unroll
        for (int t = 0; t < 4; t++) {
            const int idx = tid + t * 256;
            const int row = idx >> 3;
            const int kp  = (idx & 7) * 8;
            const int gk  = kb + kp;
            const int gm  = bm + row;
            const uint32_t dst = sA + ((buf * ASTAGE + row * 72 + kp) << 1);
            const __half* src;
            if (CONCAT == 0) {
                src = A + (size_t)gm * lda + gk;
            } else if (CONCAT == 1) {
                src = (gk < 32) ? (S1 + gm * 32 + gk)
                                : (S2 + (size_t)gm * PH_STR + (gk - 32));
            } else if (CONCAT == 3) {
                const int e = gk / KPE1;
                const int i = gk - e * KPE1;
                if (i < 32)       src = S1 + gm * 32 + i;
                else if (i < 288) src = S3 + (size_t)gm * 256 + (i - 32);
                else              src = S2 + (size_t)gm * PH_STR + (i - 288);
            } else {
                const int e = gk / KPE23;
                const int i = gk - e * KPE23;
                src = (i < 32) ? (S1 + gm * 32 + i)
                               : (S2 + (size_t)gm * 256 + (i - 32));
            }
            cp16(dst, src, true);
        }
#pragma unroll
        for (int t = 0; t < 4; t++) {
            const int idx = tid + t * 256;
            const int n   = idx >> 3;
            const int kp  = (idx & 7) * 8;
            const int gn  = n0 + n;
            const uint32_t dst = sB + ((buf * BSTAGE + n * 72 + kp) << 1);
            cp16(dst, Wt + (size_t)gn * K + kb + kp, gn < N);
        }
        cp_commit();
    };

    auto compute = [&](int buf, int e) {
        const uint32_t uA = sA + ((buf * ASTAGE) << 1);
        const uint32_t uB = sB + ((buf * BSTAGE) << 1);
        uint32_t s[4][2];
        if (SCALED) {
#pragma unroll
            for (int mt = 0; mt < 4; mt++) {
                const int rb = warp_m * 64 + mt * 16 + r0;
                const float w0 = ws[rb * NEXP + e];
                const float w1 = ws[(rb + 8) * NEXP + e];
                const __half2 h0 = __floats2half2_rn(w0, w0);
                const __half2 h1 = __floats2half2_rn(w1, w1);
                s[mt][0] = *(const uint32_t*)&h0;
                s[mt][1] = *(const uint32_t*)&h1;
            }
        }
#pragma unroll
        for (int kh = 0; kh < 2; kh++) {
            uint32_t bfr[4][4];
#pragma unroll
            for (int nt = 0; nt < 4; nt++) {
                const int brow = warp_n * 32 + nt * 8 + (lane & 7);
                ldsm4(bfr[nt], uB + ((brow * 72 + kh * 32 + (lane >> 3) * 8) << 1));
            }
#pragma unroll
            for (int ks = 0; ks < 2; ks++) {
                uint32_t a[4][4];
#pragma unroll
                for (int mt = 0; mt < 4; mt++) {
                    ldsm4(a[mt], uA + (((lrow + mt * 16) * 72 + kh * 32 + ks * 16 + alcol) << 1));
                    if (SCALED) {
                        a[mt][0] = hmul2u(a[mt][0], s[mt][0]);
                        a[mt][1] = hmul2u(a[mt][1], s[mt][1]);
                        a[mt][2] = hmul2u(a[mt][2], s[mt][0]);
                        a[mt][3] = hmul2u(a[mt][3], s[mt][1]);
                    }
                }
#pragma unroll
                for (int mt = 0; mt < 4; mt++)
#pragma unroll
                    for (int nt = 0; nt < 4; nt++)
                        mma16(d[mt][nt], a[mt], &bfr[nt][ks * 2]);
            }
        }
    };

    // prologue: get the first copy batch in flight BEFORE the omega preload
    issue(0);
    if (SCALED) {
        for (int i = tid; i < 128 * NEXP; i += 256) ws[i] = omega[bm * NEXP + i];
    }
    // single-sync double-buffered mainloop: issue(c+1) sits AFTER the barrier,
    // so the buffer it overwrites (read in compute(c-1)) is provably free.
    for (int c = 0; c < NC; c++) {
        cp_wait<0>();
        __syncthreads();
        if (c + 1 < NC) issue(c + 1);
        if (SCALED && (c % CPE) == CPE - 1) {
            if (tid < 128) As[(c & 1) * ASTAGE + tid * 72 + BCOL] = __float2half_rn(1.0f);
            __syncthreads();
        }
        compute(c & 1, SCALED ? (c / CPE) : 0);
    }

    if (SMAX) {
        // ---- fused gate-L3 + softmax epilogue (N == 128 tile holds full row) ----
        __syncthreads();                       // mainloop smem reads done
        float* epi = (float*)smh;              // 128 x 133
        float* g3  = (float*)smh + 128 * 133;  // 128*5 gw3 + 5 gb3
        for (int i = tid; i < 128 * NEXP; i += 256) g3[i] = gw3[i];
        if (tid < NEXP) g3[128 * NEXP + tid] = gb3[tid];
#pragma unroll
        for (int mt = 0; mt < 4; mt++) {
#pragma unroll
            for (int half_ = 0; half_ < 2; half_++) {
                const int lm = warp_m * 64 + mt * 16 + r0 + half_ * 8;
#pragma unroll
                for (int nt = 0; nt < 4; nt++) {
                    const int ln = warp_n * 32 + nt * 8 + c0 * 2;
                    float v0 = d[mt][nt][half_ * 2 + 0] + bias[ln];
                    float v1 = d[mt][nt][half_ * 2 + 1] + bias[ln + 1];
                    v0 = (v0 > 0.f) ? v0 : expm1f(v0);
                    v1 = (v1 > 0.f) ? v1 : expm1f(v1);
                    epi[lm * 133 + ln]     = v0;
                    epi[lm * 133 + ln + 1] = v1;
                }
            }
        }
        __syncthreads();
        if (tid < 128) {
            float p[NEXP];
#pragma unroll
            for (int e = 0; e < NEXP; e++) p[e] = g3[128 * NEXP + e];
            const float* row = epi + tid * 133;
            for (int k = 0; k < 128; k++) {
                const float x = row[k];
#pragma unroll
                for (int e = 0; e < NEXP; e++) p[e] = fmaf(x, g3[k * NEXP + e], p[e]);
            }
            float mx = -1e30f;
#pragma unroll
            for (int e = 0; e < NEXP; e++) mx = fmaxf(mx, p[e]);
            float sum = 0.f;
#pragma unroll
            for (int e = 0; e < NEXP; e++) { p[e] = expf(p[e] - mx); sum += p[e]; }
            const float inv = 1.f / sum;
#pragma unroll
            for (int e = 0; e < NEXP; e++) omega_out[(bm + tid) * NEXP + e] = p[e] * inv;
        }
        return;
    }

    // ---- standard epilogue ----
#pragma unroll
    for (int mt = 0; mt < 4; mt++) {
#pragma unroll
        for (int half_ = 0; half_ < 2; half_++) {
            const int gm = bm + warp_m * 64 + mt * 16 + r0 + half_ * 8;
#pragma unroll
            for (int nt = 0; nt < 4; nt++) {
                const int gn = n0 + warp_n * 32 + nt * 8 + c0 * 2;
                if (gn < N) {
                    float v0 = d[mt][nt][half_ * 2 + 0];
                    float v1 = d[mt][nt][half_ * 2 + 1];
                    if (HAS_BIAS) { v0 += bias[gn]; v1 += bias[gn + 1]; }
                    if (DO_ELU) {
                        v0 = (v0 > 0.f) ? v0 : expm1f(v0);
                        v1 = (v1 > 0.f) ? v1 : expm1f(v1);
                    }
                    if (OUT_HALF)
                        *(__half2*)((__half*)C + (size_t)gm * ldc + gn) = __floats2half2_rn(v0, v1);
                    else
                        *(float2*)((float*)C + (size_t)gm * ldc + gn) = make_float2(v0, v1);
                }
            }
        }
    }
}

// ---------------- merged weight convert+transpose ----------------------------
struct CvtJobs {
    const float* src[8];
    const float* bias[8];
    __half*      dst[8];
    int Kd[8], KP[8], N[8], mode[8];
    int blkOff[9];
};

__global__ void cvtT_all(CvtJobs J)
{
    __shared__ float t[32][33];
    int b = blockIdx.x, j = 0;
    while (b >= J.blkOff[j + 1]) j++;
    const int local = b - J.blkOff[j];
    const int nbN = (J.N[j] + 31) / 32;
    const int nb = (local % nbN) * 32;
    const int kb = (local / nbN) * 32;
    const int N = J.N[j], KP = J.KP[j], Kd = J.Kd[j], mode = J.mode[j];
    const float* src = J.src[j];
    const float* bias = J.bias[j];
    __half* dst = J.dst[j];
    const int tx = threadIdx.x & 31, ty = threadIdx.x >> 5;

    for (int r = ty; r < 32; r += 8) {
        const int k = kb + r, n = nb + tx;
        float v = 0.f;
        if (n < N && k < KP) {
            if (mode == 0) {
                if (k < Kd) v = src[(size_t)k * N + n];
            } else if (mode == 1) {
                const int e = k / KPE1, rr = k - e * KPE1;
                if (rr < 32)       v = src[(size_t)(e * 812 + rr) * N + n];
                else if (rr < 288) v = src[(size_t)(e * 812 + 556 + (rr - 32)) * N + n];
                else if (rr < 812) v = src[(size_t)(e * 812 + 32 + (rr - 288)) * N + n];
                else if (rr == 812) v = bias[e * N + n];
            } else {
                const int e = k / KPE23, rr = k - e * KPE23;
                if (rr < 288)       v = src[(size_t)(e * 288 + rr) * N + n];
                else if (rr == 288) v = bias[e * N + n];
            }
        }
        t[r][tx] = v;
    }
    __syncthreads();
    for (int r = ty; r < 32; r += 8) {
        const int n = nb + r, k = kb + tx;
        if (n < N && k < KP) dst[(size_t)n * KP + k] = __float2half_rn(t[tx][r]);
    }
}

// ---------------- merged input converts (I, z, p) ----------------------------
#define NI8 (BATCH * 256)
#define NZ8 (BATCH * 4)
#define NP8 (BATCH * 66)
__global__ void cvt_inputs(const float* __restrict__ I, const float* __restrict__ z,
                           const float* __restrict__ p,
                           __half* __restrict__ Ih, __half* __restrict__ zh,
                           __half* __restrict__ ph)
{
    const int idx = blockIdx.x * blockDim.x + threadIdx.x;
    if (idx < NI8 + NZ8) {
        const float* s = (idx < NI8) ? (I + (size_t)idx * 8) : (z + (size_t)(idx - NI8) * 8);
        __half* dpt    = (idx < NI8) ? (Ih + (size_t)idx * 8) : (zh + (size_t)(idx - NI8) * 8);
        const float4 v0 = ((const float4*)s)[0];
        const float4 v1 = ((const float4*)s)[1];
        __half2 h[4];
        h[0] = __floats2half2_rn(v0.x, v0.y);
        h[1] = __floats2half2_rn(v0.z, v0.w);
        h[2] = __floats2half2_rn(v1.x, v1.y);
        h[3] = __floats2half2_rn(v1.z, v1.w);
        *(uint4*)dpt = *(uint4*)h;
    } else if (idx < NI8 + NZ8 + NP8) {
        const int jj = idx - NI8 - NZ8;
        const int m = jj / 66;
        const int c = (jj - m * 66) * 8;
        __half h[8];
#pragma unroll
        for (int k = 0; k < 8; k++)
            h[k] = (c + k < 524) ? __float2half_rn(p[(size_t)m * 524 + c + k]) : __float2half_rn(0.f);
        *(uint4*)(ph + (size_t)m * PH_STR + c) = *(uint4*)h;
    }
}

// ---------------- launcher ----------------------------------------------------
extern "C" void kernel_launch(void* const* d_in, const int* in_sizes, int n_in,
                              void* d_out, int out_size)
{
    const float* z      = (const float*)d_in[0];
    const float* p_prev = (const float*)d_in[1];
    const float* I      = (const float*)d_in[2];
    const float* gw1 = (const float*)d_in[3];  const float* gb1 = (const float*)d_in[4];
    const float* gw2 = (const float*)d_in[5];  const float* gb2 = (const float*)d_in[6];
    const float* gw3 = (const float*)d_in[7];  const float* gb3 = (const float*)d_in[8];
    const float* iw1 = (const float*)d_in[9];  const float* ib1 = (const float*)d_in[10];
    const float* iw2 = (const float*)d_in[11]; const float* ib2 = (const float*)d_in[12];
    const float* iw3 = (const float*)d_in[13]; const float* ib3 = (const float*)d_in[14];
    const float* wl1 = (const float*)d_in[15]; const float* bl1 = (const float*)d_in[16];
    const float* wl2 = (const float*)d_in[17]; const float* bl2 = (const float*)d_in[18];
    const float* wl3 = (const float*)d_in[19]; const float* bl3 = (const float*)d_in[20];
    float* out = (float*)d_out;

    __half *Ih, *zh, *ph, *bufA, *bufB, *h1, *h2;
    __half *tiw1, *tiw2, *tiw3, *tgw1, *tgw2, *twl1, *twl2, *twl3;
    float *omega;
    cudaGetSymbolAddress((void**)&Ih,    d_Ih);
    cudaGetSymbolAddress((void**)&zh,    d_zh);
    cudaGetSymbolAddress((void**)&ph,    d_ph);
    cudaGetSymbolAddress((void**)&bufA,  d_bufA);
    cudaGetSymbolAddress((void**)&bufB,  d_bufB);
    cudaGetSymbolAddress((void**)&omega, d_omega);
    cudaGetSymbolAddress((void**)&h1,    d_h1);
    cudaGetSymbolAddress((void**)&h2,    d_h2);
    cudaGetSymbolAddress((void**)&tiw1,  d_tiw1);
    cudaGetSymbolAddress((void**)&tiw2,  d_tiw2);
    cudaGetSymbolAddress((void**)&tiw3,  d_tiw3);
    cudaGetSymbolAddress((void**)&tgw1,  d_tgw1);
    cudaGetSymbolAddress((void**)&tgw2,  d_tgw2);
    cudaGetSymbolAddress((void**)&twl1,  d_twl1);
    cudaGetSymbolAddress((void**)&twl2,  d_twl2);
    cudaGetSymbolAddress((void**)&twl3,  d_twl3);

    auto kPlain = mma_gemm<0, false, 1, 0,  true,  true,  true,  false>;
    auto kGate1 = mma_gemm<1, false, 1, 0,  true,  true,  true,  false>;
    auto kGate2 = mma_gemm<0, false, 1, 0,  true,  true,  true,  true>;   // SMAX
    auto kMoe1  = mma_gemm<3, true, 13, 44, false, true,  true,  false>;
    auto kMoe2  = mma_gemm<4, true, 5,  32, false, true,  true,  false>;
    auto kMoe3  = mma_gemm<4, true, 5,  32, false, false, false, false>;
    const int SMEM = 4 * 128 * 72 * 2 + 128 * NEXP * 4;   // 76288 B
    cudaFuncSetAttribute((const void*)kPlain, cudaFuncAttributeMaxDynamicSharedMemorySize, SMEM);
    cudaFuncSetAttribute((const void*)kGate1, cudaFuncAttributeMaxDynamicSharedMemorySize, SMEM);
    cudaFuncSetAttribute((const void*)kGate2, cudaFuncAttributeMaxDynamicSharedMemorySize, SMEM);
    cudaFuncSetAttribute((const void*)kMoe1,  cudaFuncAttributeMaxDynamicSharedMemorySize, SMEM);
    cudaFuncSetAttribute((const void*)kMoe2,  cudaFuncAttributeMaxDynamicSharedMemorySize, SMEM);
    cudaFuncSetAttribute((const void*)kMoe3,  cudaFuncAttributeMaxDynamicSharedMemorySize, SMEM);

    // ---- merged weight converts ----
    CvtJobs J;
    const float* srcs[8]  = {iw1, iw2, iw3, gw1, gw2, wl1, wl2, wl3};
    const float* biass[8] = {nullptr, nullptr, nullptr, nullptr, nullptr, bl1, bl2, bl3};
    __half* dsts[8]       = {tiw1, tiw2, tiw3, tgw1, tgw2, twl1, twl2, twl3};
    const int Kds[8]   = {2048, 256, 256, 556, 256, 0, 0, 0};
    const int KPs[8]   = {2048, 256, 256, KP_GATE1, 256, KP_MOE1, KP_MOE23, KP_MOE23};
    const int Ns[8]    = {256, 256, 256, 256, 128, 256, 256, 524};
    const int modes[8] = {0, 0, 0, 0, 0, 1, 2, 2};
    int off = 0;
    for (int j = 0; j < 8; j++) {
        J.src[j] = srcs[j]; J.bias[j] = biass[j]; J.dst[j] = dsts[j];
        J.Kd[j] = Kds[j]; J.KP[j] = KPs[j]; J.N[j] = Ns[j]; J.mode[j] = modes[j];
        J.blkOff[j] = off;
        off += ((Ns[j] + 31) / 32) * (KPs[j] / 32);
    }
    J.blkOff[8] = off;

    const dim3 blk(256);
    cvtT_all<<<off, blk>>>(J);
    cvt_inputs<<<(NI8 + NZ8 + NP8 + 255) / 256, blk>>>(I, z, p_prev, Ih, zh, ph);

    const dim3 gN256(2, BATCH / 128);
    const dim3 gN128(1, BATCH / 128);
    const dim3 gN524(5, BATCH / 128);

    // INet: 2048 -> 256 -> 256 -> 256 (ELU)
    kPlain<<<gN256, blk, SMEM>>>(Ih,   2048, nullptr, nullptr, nullptr, nullptr, tiw1, ib1, nullptr, nullptr, nullptr, bufA, 256, 256, 2048);
    kPlain<<<gN256, blk, SMEM>>>(bufA,  256, nullptr, nullptr, nullptr, nullptr, tiw2, ib2, nullptr, nullptr, nullptr, bufB, 256, 256,  256);
    kPlain<<<gN256, blk, SMEM>>>(bufB,  256, nullptr, nullptr, nullptr, nullptr, tiw3, ib3, nullptr, nullptr, nullptr, bufA, 256, 256,  256);

    // gating: [z|p_prev] -> 256 -> (128 -> 5 + softmax fused)
    kGate1<<<gN256, blk, SMEM>>>(nullptr, 0, zh, ph, nullptr, nullptr, tgw1, gb1, nullptr, nullptr, nullptr, bufB, 256, 256, KP_GATE1);
    kGate2<<<gN128, blk, SMEM>>>(bufB, 256, nullptr, nullptr, nullptr, nullptr, tgw2, gb2, gw3, gb3, omega, nullptr, 128, 128, 256);

    // MoE layers: fused omega-scaled expert blocks, bias folded as 1-row
    kMoe1<<<gN256, blk, SMEM>>>(nullptr, 0, zh, ph, bufA, omega, twl1, nullptr, nullptr, nullptr, nullptr, h1, 256, 256, KP_MOE1);
    kMoe2<<<gN256, blk, SMEM>>>(nullptr, 0, zh, h1, nullptr, omega, twl2, nullptr, nullptr, nullptr, nullptr, h2, 256, 256, KP_MOE23);
    kMoe3<<<gN524, blk, SMEM>>>(nullptr, 0, zh, h2, nullptr, omega, twl3, nullptr, nullptr, nullptr, nullptr, out, 524, 524, KP_MOE23);
}

// round 17
// speedup vs baseline: 1.5087x; 1.5087x over previous
#include <cuda_runtime.h>
#include <cuda_fp16.h>
#include <math.h>
#include <cstdint>

#define BATCH 16384
#define NEXP  5

#define KP_MOE1  4160   // 5 * 832
#define KPE1     832
#define KP_MOE23 1600   // 5 * 320
#define KPE23    320
#define KP_GATE1 576
#define PH_STR   528

// ---------------- scratch (static device globals; no allocation) ------------
__device__ __half d_Ih  [(size_t)BATCH * 2048];
__device__ __half d_zh  [BATCH * 32];
__device__ __half d_ph  [(size_t)BATCH * PH_STR + 64];
__device__ __half d_bufA[BATCH * 256];            // inet ping / ienc
__device__ __half d_bufB[BATCH * 256];
__device__ float  d_omega[BATCH * NEXP];
__device__ __half d_h1  [BATCH * 256 + 64];
__device__ __half d_h2  [BATCH * 256 + 64];
// transposed half weights [N][KP]
__device__ __half d_tiw1[256 * 2048], d_tiw2[256 * 256], d_tiw3[256 * 256];
__device__ __half d_tgw1[256 * KP_GATE1], d_tgw2[128 * 256];
__device__ __half d_twl1[256 * KP_MOE1], d_twl2[256 * KP_MOE23], d_twl3[524 * KP_MOE23];

// ---------------- helpers ----------------------------------------------------
__device__ __forceinline__ void mma16(float* d, const uint32_t* a, const uint32_t* b) {
    asm volatile(
        "mma.sync.aligned.m16n8k16.row.col.f32.f16.f16.f32 "
        "{%0,%1,%2,%3}, {%4,%5,%6,%7}, {%8,%9}, {%0,%1,%2,%3};"
        : "+f"(d[0]), "+f"(d[1]), "+f"(d[2]), "+f"(d[3])
        : "r"(a[0]), "r"(a[1]), "r"(a[2]), "r"(a[3]), "r"(b[0]), "r"(b[1]));
}
__device__ __forceinline__ void ldsm4(uint32_t* r, uint32_t addr) {
    asm volatile("ldmatrix.sync.aligned.m8n8.x4.shared.b16 {%0,%1,%2,%3}, [%4];"
                 : "=r"(r[0]), "=r"(r[1]), "=r"(r[2]), "=r"(r[3]) : "r"(addr));
}
__device__ __forceinline__ void cp16(uint32_t dst, const void* src, bool ok) {
    asm volatile("cp.async.cg.shared.global [%0], [%1], 16, %2;"
                 :: "r"(dst), "l"(src), "r"(ok ? 16 : 0) : "memory");
}
__device__ __forceinline__ void cp_commit() {
    asm volatile("cp.async.commit_group;" ::: "memory");
}
template <int NPEND> __device__ __forceinline__ void cp_wait() {
    asm volatile("cp.async.wait_group %0;" :: "n"(NPEND) : "memory");
}
__device__ __forceinline__ uint32_t hmul2u(uint32_t a, uint32_t s) {
    __half2 ha = *(__half2*)&a;
    __half2 hs = *(__half2*)&s;
    __half2 r = __hmul2(ha, hs);
    return *(uint32_t*)&r;
}

// ---------------- fp16 tensor-core GEMM --------------------------------------
// Block 128x128x64, 256 threads, warps 2x4, warp tile 64x32.
// Single-__syncthreads double-buffered cp.async mainloop.
// CONCAT 0: A'[m,k]=A[m*lda+k]
// CONCAT 1: gate1 concat  (zh:32 | ph strided)
// CONCAT 3: moe1 expert blocks of 832: z(32)|ienc(256)|p(524)|bias1|pad
// CONCAT 4: moe23 expert blocks of 320: z(32)|h(256)|bias1|pad
// SCALED: scale A fragments by omega[row][e], e = chunk/CPE; expert's last
//         chunk carries a 1.0 column at BCOL (bias row of Wt).
// SMAX: replace epilogue with 128->5 projection (gw3,gb3) + softmax -> omega_out
template <int CONCAT, bool SCALED, int CPE, int BCOL, bool HAS_BIAS, bool DO_ELU,
          bool OUT_HALF, bool SMAX>
__global__ __launch_bounds__(256, 2)
void mma_gemm(const __half* __restrict__ A, int lda,
              const __half* __restrict__ S1, const __half* __restrict__ S2,
              const __half* __restrict__ S3,
              const float* __restrict__ omega,
              const __half* __restrict__ Wt, const float* __restrict__ bias,
              const float* __restrict__ gw3, const float* __restrict__ gb3,
              float* __restrict__ omega_out,
              void* __restrict__ C, int ldc, int N, int K)
{
    constexpr int ASTAGE = 128 * 72;   // halves
    constexpr int BSTAGE = 128 * 72;
    extern __shared__ __half smh[];
    __half* As = smh;
    __half* Bs = smh + 2 * ASTAGE;
    float*  ws = (float*)(smh + 4 * ASTAGE);   // 128 x 5 omega

    const int tid    = threadIdx.x;
    const int wid    = tid >> 5;
    const int lane   = tid & 31;
    const int warp_m = wid & 1;
    const int warp_n = wid >> 1;
    const int bm     = blockIdx.y * 128;
    const int n0     = blockIdx.x * 128;
    const int r0     = lane >> 2;
    const int c0     = lane & 3;

    const uint32_t sA = (uint32_t)__cvta_generic_to_shared(As);
    const uint32_t sB = (uint32_t)__cvta_generic_to_shared(Bs);

    const int lrow  = warp_m * 64 + (lane & 7) + ((lane >> 3) & 1) * 8;
    const int alcol = (lane >> 4) * 8;

    if (SCALED) {
        for (int i = tid; i < 128 * NEXP; i += 256) ws[i] = omega[bm * NEXP + i];
    }

    float d[4][4][4];
#pragma unroll
    for (int mt = 0; mt < 4; mt++)
#pragma unroll
        for (int nt = 0; nt < 4; nt++)
#pragma unroll
            for (int r = 0; r < 4; r++) d[mt][nt][r] = 0.f;

    const int NC = K >> 6;

    auto issue = [&](int c) {
        const int kb  = c * 64;
        const int buf = c & 1;
#pragma unroll
        for (int t = 0; t < 4; t++) {
            const int idx = tid + t * 256;
            const int row = idx >> 3;
            const int kp  = (idx & 7) * 8;
            const int gk  = kb + kp;
            const int gm  = bm + row;
            const uint32_t dst = sA + ((buf * ASTAGE + row * 72 + kp) << 1);
            const __half* src;
            if (CONCAT == 0) {
                src = A + (size_t)gm * lda + gk;
            } else if (CONCAT == 1) {
                src = (gk < 32) ? (S1 + gm * 32 + gk)
                                : (S2 + (size_t)gm * PH_STR + (gk - 32));
            } else if (CONCAT == 3) {
                const int e = gk / KPE1;
                const int i = gk - e * KPE1;
                if (i < 32)       src = S1 + gm * 32 + i;
                else if (i < 288) src = S3 + (size_t)gm * 256 + (i - 32);
                else              src = S2 + (size_t)gm * PH_STR + (i - 288);
            } else {
                const int e = gk / KPE23;
                const int i = gk - e * KPE23;
                src = (i < 32) ? (S1 + gm * 32 + i)
                               : (S2 + (size_t)gm * 256 + (i - 32));
            }
            cp16(dst, src, true);
        }
#pragma unroll
        for (int t = 0; t < 4; t++) {
            const int idx = tid + t * 256;
            const int n   = idx >> 3;
            const int kp  = (idx & 7) * 8;
            const int gn  = n0 + n;
            const uint32_t dst = sB + ((buf * BSTAGE + n * 72 + kp) << 1);
            cp16(dst, Wt + (size_t)gn * K + kb + kp, gn < N);
        }
        cp_commit();
    };

    auto compute = [&](int buf, int e) {
        const uint32_t uA = sA + ((buf * ASTAGE) << 1);
        const uint32_t uB = sB + ((buf * BSTAGE) << 1);
        uint32_t s[4][2];
        if (SCALED) {
#pragma unroll
            for (int mt = 0; mt < 4; mt++) {
                const int rb = warp_m * 64 + mt * 16 + r0;
                const float w0 = ws[rb * NEXP + e];
                const float w1 = ws[(rb + 8) * NEXP + e];
                const __half2 h0 = __floats2half2_rn(w0, w0);
                const __half2 h1 = __floats2half2_rn(w1, w1);
                s[mt][0] = *(const uint32_t*)&h0;
                s[mt][1] = *(const uint32_t*)&h1;
            }
        }
#pragma unroll
        for (int kh = 0; kh < 2; kh++) {
            uint32_t bfr[4][4];
#pragma unroll
            for (int nt = 0; nt < 4; nt++) {
                const int brow = warp_n * 32 + nt * 8 + (lane & 7);
                ldsm4(bfr[nt], uB + ((brow * 72 + kh * 32 + (lane >> 3) * 8) << 1));
            }
#pragma unroll
            for (int ks = 0; ks < 2; ks++) {
                uint32_t a[4][4];
#pragma unroll
                for (int mt = 0; mt < 4; mt++) {
                    ldsm4(a[mt], uA + (((lrow + mt * 16) * 72 + kh * 32 + ks * 16 + alcol) << 1));
                    if (SCALED) {
                        a[mt][0] = hmul2u(a[mt][0], s[mt][0]);
                        a[mt][1] = hmul2u(a[mt][1], s[mt][1]);
                        a[mt][2] = hmul2u(a[mt][2], s[mt][0]);
                        a[mt][3] = hmul2u(a[mt][3], s[mt][1]);
                    }
                }
#pragma unroll
                for (int mt = 0; mt < 4; mt++)
#pragma unroll
                    for (int nt = 0; nt < 4; nt++)
                        mma16(d[mt][nt], a[mt], &bfr[nt][ks * 2]);
            }
        }
    };

    // single-sync double-buffered mainloop: issue(c+1) sits AFTER the barrier,
    // so the buffer it overwrites (read in compute(c-1)) is provably free.
    issue(0);
    for (int c = 0; c < NC; c++) {
        cp_wait<0>();
        __syncthreads();
        if (c + 1 < NC) issue(c + 1);
        if (SCALED && (c % CPE) == CPE - 1) {
            if (tid < 128) As[(c & 1) * ASTAGE + tid * 72 + BCOL] = __float2half_rn(1.0f);
            __syncthreads();
        }
        compute(c & 1, SCALED ? (c / CPE) : 0);
    }

    if (SMAX) {
        // ---- fused gate-L3 + softmax epilogue (N == 128 tile holds full row) ----
        __syncthreads();                       // mainloop smem reads done
        float* epi = (float*)smh;              // 128 x 133
        float* g3  = (float*)smh + 128 * 133;  // 128*5 gw3 + 5 gb3
        for (int i = tid; i < 128 * NEXP; i += 256) g3[i] = gw3[i];
        if (tid < NEXP) g3[128 * NEXP + tid] = gb3[tid];
#pragma unroll
        for (int mt = 0; mt < 4; mt++) {
#pragma unroll
            for (int half_ = 0; half_ < 2; half_++) {
                const int lm = warp_m * 64 + mt * 16 + r0 + half_ * 8;
#pragma unroll
                for (int nt = 0; nt < 4; nt++) {
                    const int ln = warp_n * 32 + nt * 8 + c0 * 2;
                    float v0 = d[mt][nt][half_ * 2 + 0] + bias[ln];
                    float v1 = d[mt][nt][half_ * 2 + 1] + bias[ln + 1];
                    v0 = (v0 > 0.f) ? v0 : expm1f(v0);
                    v1 = (v1 > 0.f) ? v1 : expm1f(v1);
                    epi[lm * 133 + ln]     = v0;
                    epi[lm * 133 + ln + 1] = v1;
                }
            }
        }
        __syncthreads();
        if (tid < 128) {
            float p[NEXP];
#pragma unroll
            for (int e = 0; e < NEXP; e++) p[e] = g3[128 * NEXP + e];
            const float* row = epi + tid * 133;
            for (int k = 0; k < 128; k++) {
                const float x = row[k];
#pragma unroll
                for (int e = 0; e < NEXP; e++) p[e] = fmaf(x, g3[k * NEXP + e], p[e]);
            }
            float mx = -1e30f;
#pragma unroll
            for (int e = 0; e < NEXP; e++) mx = fmaxf(mx, p[e]);
            float sum = 0.f;
#pragma unroll
            for (int e = 0; e < NEXP; e++) { p[e] = expf(p[e] - mx); sum += p[e]; }
            const float inv = 1.f / sum;
#pragma unroll
            for (int e = 0; e < NEXP; e++) omega_out[(bm + tid) * NEXP + e] = p[e] * inv;
        }
        return;
    }

    // ---- standard epilogue ----
#pragma unroll
    for (int mt = 0; mt < 4; mt++) {
#pragma unroll
        for (int half_ = 0; half_ < 2; half_++) {
            const int gm = bm + warp_m * 64 + mt * 16 + r0 + half_ * 8;
#pragma unroll
            for (int nt = 0; nt < 4; nt++) {
                const int gn = n0 + warp_n * 32 + nt * 8 + c0 * 2;
                if (gn < N) {
                    float v0 = d[mt][nt][half_ * 2 + 0];
                    float v1 = d[mt][nt][half_ * 2 + 1];
                    if (HAS_BIAS) { v0 += bias[gn]; v1 += bias[gn + 1]; }
                    if (DO_ELU) {
                        v0 = (v0 > 0.f) ? v0 : expm1f(v0);
                        v1 = (v1 > 0.f) ? v1 : expm1f(v1);
                    }
                    if (OUT_HALF)
                        *(__half2*)((__half*)C + (size_t)gm * ldc + gn) = __floats2half2_rn(v0, v1);
                    else
                        *(float2*)((float*)C + (size_t)gm * ldc + gn) = make_float2(v0, v1);
                }
            }
        }
    }
}

// ---------------- merged weight convert+transpose ----------------------------
struct CvtJobs {
    const float* src[8];
    const float* bias[8];
    __half*      dst[8];
    int Kd[8], KP[8], N[8], mode[8];
    int blkOff[9];
};

__global__ void cvtT_all(CvtJobs J)
{
    __shared__ float t[32][33];
    int b = blockIdx.x, j = 0;
    while (b >= J.blkOff[j + 1]) j++;
    const int local = b - J.blkOff[j];
    const int nbN = (J.N[j] + 31) / 32;
    const int nb = (local % nbN) * 32;
    const int kb = (local / nbN) * 32;
    const int N = J.N[j], KP = J.KP[j], Kd = J.Kd[j], mode = J.mode[j];
    const float* src = J.src[j];
    const float* bias = J.bias[j];
    __half* dst = J.dst[j];
    const int tx = threadIdx.x & 31, ty = threadIdx.x >> 5;

    for (int r = ty; r < 32; r += 8) {
        const int k = kb + r, n = nb + tx;
        float v = 0.f;
        if (n < N && k < KP) {
            if (mode == 0) {
                if (k < Kd) v = src[(size_t)k * N + n];
            } else if (mode == 1) {
                const int e = k / KPE1, rr = k - e * KPE1;
                if (rr < 32)       v = src[(size_t)(e * 812 + rr) * N + n];
                else if (rr < 288) v = src[(size_t)(e * 812 + 556 + (rr - 32)) * N + n];
                else if (rr < 812) v = src[(size_t)(e * 812 + 32 + (rr - 288)) * N + n];
                else if (rr == 812) v = bias[e * N + n];
            } else {
                const int e = k / KPE23, rr = k - e * KPE23;
                if (rr < 288)       v = src[(size_t)(e * 288 + rr) * N + n];
                else if (rr == 288) v = bias[e * N + n];
            }
        }
        t[r][tx] = v;
    }
    __syncthreads();
    for (int r = ty; r < 32; r += 8) {
        const int n = nb + r, k = kb + tx;
        if (n < N && k < KP) dst[(size_t)n * KP + k] = __float2half_rn(t[tx][r]);
    }
}

// ---------------- merged input converts (I, z, p) ----------------------------
#define NI8 (BATCH * 256)
#define NZ8 (BATCH * 4)
#define NP8 (BATCH * 66)
__global__ void cvt_inputs(const float* __restrict__ I, const float* __restrict__ z,
                           const float* __restrict__ p,
                           __half* __restrict__ Ih, __half* __restrict__ zh,
                           __half* __restrict__ ph)
{
    const int idx = blockIdx.x * blockDim.x + threadIdx.x;
    if (idx < NI8 + NZ8) {
        const float* s = (idx < NI8) ? (I + (size_t)idx * 8) : (z + (size_t)(idx - NI8) * 8);
        __half* dpt    = (idx < NI8) ? (Ih + (size_t)idx * 8) : (zh + (size_t)(idx - NI8) * 8);
        const float4 v0 = ((const float4*)s)[0];
        const float4 v1 = ((const float4*)s)[1];
        __half2 h[4];
        h[0] = __floats2half2_rn(v0.x, v0.y);
        h[1] = __floats2half2_rn(v0.z, v0.w);
        h[2] = __floats2half2_rn(v1.x, v1.y);
        h[3] = __floats2half2_rn(v1.z, v1.w);
        *(uint4*)dpt = *(uint4*)h;
    } else if (idx < NI8 + NZ8 + NP8) {
        const int jj = idx - NI8 - NZ8;
        const int m = jj / 66;
        const int c = (jj - m * 66) * 8;
        __half h[8];
#pragma unroll
        for (int k = 0; k < 8; k++)
            h[k] = (c + k < 524) ? __float2half_rn(p[(size_t)m * 524 + c + k]) : __float2half_rn(0.f);
        *(uint4*)(ph + (size_t)m * PH_STR + c) = *(uint4*)h;
    }
}

// ---------------- launcher ----------------------------------------------------
extern "C" void kernel_launch(void* const* d_in, const int* in_sizes, int n_in,
                              void* d_out, int out_size)
{
    const float* z      = (const float*)d_in[0];
    const float* p_prev = (const float*)d_in[1];
    const float* I      = (const float*)d_in[2];
    const float* gw1 = (const float*)d_in[3];  const float* gb1 = (const float*)d_in[4];
    const float* gw2 = (const float*)d_in[5];  const float* gb2 = (const float*)d_in[6];
    const float* gw3 = (const float*)d_in[7];  const float* gb3 = (const float*)d_in[8];
    const float* iw1 = (const float*)d_in[9];  const float* ib1 = (const float*)d_in[10];
    const float* iw2 = (const float*)d_in[11]; const float* ib2 = (const float*)d_in[12];
    const float* iw3 = (const float*)d_in[13]; const float* ib3 = (const float*)d_in[14];
    const float* wl1 = (const float*)d_in[15]; const float* bl1 = (const float*)d_in[16];
    const float* wl2 = (const float*)d_in[17]; const float* bl2 = (const float*)d_in[18];
    const float* wl3 = (const float*)d_in[19]; const float* bl3 = (const float*)d_in[20];
    float* out = (float*)d_out;

    __half *Ih, *zh, *ph, *bufA, *bufB, *h1, *h2;
    __half *tiw1, *tiw2, *tiw3, *tgw1, *tgw2, *twl1, *twl2, *twl3;
    float *omega;
    cudaGetSymbolAddress((void**)&Ih,    d_Ih);
    cudaGetSymbolAddress((void**)&zh,    d_zh);
    cudaGetSymbolAddress((void**)&ph,    d_ph);
    cudaGetSymbolAddress((void**)&bufA,  d_bufA);
    cudaGetSymbolAddress((void**)&bufB,  d_bufB);
    cudaGetSymbolAddress((void**)&omega, d_omega);
    cudaGetSymbolAddress((void**)&h1,    d_h1);
    cudaGetSymbolAddress((void**)&h2,    d_h2);
    cudaGetSymbolAddress((void**)&tiw1,  d_tiw1);
    cudaGetSymbolAddress((void**)&tiw2,  d_tiw2);
    cudaGetSymbolAddress((void**)&tiw3,  d_tiw3);
    cudaGetSymbolAddress((void**)&tgw1,  d_tgw1);
    cudaGetSymbolAddress((void**)&tgw2,  d_tgw2);
    cudaGetSymbolAddress((void**)&twl1,  d_twl1);
    cudaGetSymbolAddress((void**)&twl2,  d_twl2);
    cudaGetSymbolAddress((void**)&twl3,  d_twl3);

    auto kPlain = mma_gemm<0, false, 1, 0,  true,  true,  true,  false>;
    auto kGate1 = mma_gemm<1, false, 1, 0,  true,  true,  true,  false>;
    auto kGate2 = mma_gemm<0, false, 1, 0,  true,  true,  true,  true>;   // SMAX
    auto kMoe1  = mma_gemm<3, true, 13, 44, false, true,  true,  false>;
    auto kMoe2  = mma_gemm<4, true, 5,  32, false, true,  true,  false>;
    auto kMoe3  = mma_gemm<4, true, 5,  32, false, false, false, false>;
    const int SMEM = 4 * 128 * 72 * 2 + 128 * NEXP * 4;   // 76288 B
    cudaFuncSetAttribute((const void*)kPlain, cudaFuncAttributeMaxDynamicSharedMemorySize, SMEM);
    cudaFuncSetAttribute((const void*)kGate1, cudaFuncAttributeMaxDynamicSharedMemorySize, SMEM);
    cudaFuncSetAttribute((const void*)kGate2, cudaFuncAttributeMaxDynamicSharedMemorySize, SMEM);
    cudaFuncSetAttribute((const void*)kMoe1,  cudaFuncAttributeMaxDynamicSharedMemorySize, SMEM);
    cudaFuncSetAttribute((const void*)kMoe2,  cudaFuncAttributeMaxDynamicSharedMemorySize, SMEM);
    cudaFuncSetAttribute((const void*)kMoe3,  cudaFuncAttributeMaxDynamicSharedMemorySize, SMEM);

    // ---- merged weight converts ----
    CvtJobs J;
    const float* srcs[8]  = {iw1, iw2, iw3, gw1, gw2, wl1, wl2, wl3};
    const float* biass[8] = {nullptr, nullptr, nullptr, nullptr, nullptr, bl1, bl2, bl3};
    __half* dsts[8]       = {tiw1, tiw2, tiw3, tgw1, tgw2, twl1, twl2, twl3};
    const int Kds[8]   = {2048, 256, 256, 556, 256, 0, 0, 0};
    const int KPs[8]   = {2048, 256, 256, KP_GATE1, 256, KP_MOE1, KP_MOE23, KP_MOE23};
    const int Ns[8]    = {256, 256, 256, 256, 128, 256, 256, 524};
    const int modes[8] = {0, 0, 0, 0, 0, 1, 2, 2};
    int off = 0;
    for (int j = 0; j < 8; j++) {
        J.src[j] = srcs[j]; J.bias[j] = biass[j]; J.dst[j] = dsts[j];
        J.Kd[j] = Kds[j]; J.KP[j] = KPs[j]; J.N[j] = Ns[j]; J.mode[j] = modes[j];
        J.blkOff[j] = off;
        off += ((Ns[j] + 31) / 32) * (KPs[j] / 32);
    }
    J.blkOff[8] = off;

    const dim3 blk(256);
    cvtT_all<<<off, blk>>>(J);
    cvt_inputs<<<(NI8 + NZ8 + NP8 + 255) / 256, blk>>>(I, z, p_prev, Ih, zh, ph);

    const dim3 gN256(2, BATCH / 128);
    const dim3 gN128(1, BATCH / 128);
    const dim3 gN524(5, BATCH / 128);

    // INet: 2048 -> 256 -> 256 -> 256 (ELU)
    kPlain<<<gN256, blk, SMEM>>>(Ih,   2048, nullptr, nullptr, nullptr, nullptr, tiw1, ib1, nullptr, nullptr, nullptr, bufA, 256, 256, 2048);
    kPlain<<<gN256, blk, SMEM>>>(bufA,  256, nullptr, nullptr, nullptr, nullptr, tiw2, ib2, nullptr, nullptr, nullptr, bufB, 256, 256,  256);
    kPlain<<<gN256, blk, SMEM>>>(bufB,  256, nullptr, nullptr, nullptr, nullptr, tiw3, ib3, nullptr, nullptr, nullptr, bufA, 256, 256,  256);

    // gating: [z|p_prev] -> 256 -> (128 -> 5 + softmax fused)
    kGate1<<<gN256, blk, SMEM>>>(nullptr, 0, zh, ph, nullptr, nullptr, tgw1, gb1, nullptr, nullptr, nullptr, bufB, 256, 256, KP_GATE1);
    kGate2<<<gN128, blk, SMEM>>>(bufB, 256, nullptr, nullptr, nullptr, nullptr, tgw2, gb2, gw3, gb3, omega, nullptr, 128, 128, 256);

    // MoE layers: fused omega-scaled expert blocks, bias folded as 1-row
    kMoe1<<<gN256, blk, SMEM>>>(nullptr, 0, zh, ph, bufA, omega, twl1, nullptr, nullptr, nullptr, nullptr, h1, 256, 256, KP_MOE1);
    kMoe2<<<gN256, blk, SMEM>>>(nullptr, 0, zh, h1, nullptr, omega, twl2, nullptr, nullptr, nullptr, nullptr, h2, 256, 256, KP_MOE23);
    kMoe3<<<gN524, blk, SMEM>>>(nullptr, 0, zh, h2, nullptr, omega, twl3, nullptr, nullptr, nullptr, nullptr, out, 524, 524, KP_MOE23);
}